// round 2
// baseline (speedup 1.0000x reference)
#include <cuda_runtime.h>
#include <cuda_bf16.h>

#define EMBED 100
#define BATCH 8192
#define FUNC_VOCAB 10000
#define VEC4_PER_MAT 2500   // 100*100/4
#define F4_PER_ROW   25     // 100/4
#define NTHREADS     256
#define ITERS        10     // ceil(2500/256)

__device__ int g_perm[BATCH];

// ---------------------------------------------------------------------------
// Single-CTA counting sort of batch indices by functor id.
// hist fits in 40 KB static smem. Output: g_perm holds batch indices grouped
// by functor, so duplicate matrices are processed by adjacent (concurrent)
// CTAs and hit L2.
// ---------------------------------------------------------------------------
__global__ __launch_bounds__(1024)
void sort_by_functor_kernel(const int* __restrict__ Xf)
{
    __shared__ int hist[FUNC_VOCAB];
    __shared__ int warp_pref[32];
    const int t = threadIdx.x;
    const int lane = t & 31, wid = t >> 5;

    for (int i = t; i < FUNC_VOCAB; i += 1024) hist[i] = 0;
    __syncthreads();

    #pragma unroll
    for (int b = t; b < BATCH; b += 1024) atomicAdd(&hist[Xf[b]], 1);
    __syncthreads();

    // Each thread owns 10 consecutive bins; build per-thread exclusive prefix.
    const int base = t * 10;
    int cnt[10];
    int local = 0;
    #pragma unroll
    for (int i = 0; i < 10; i++) {
        int idx = base + i;
        int v = (idx < FUNC_VOCAB) ? hist[idx] : 0;
        cnt[i] = local;
        local += v;
    }

    // Block-wide exclusive scan of per-thread sums.
    int x = local;
    #pragma unroll
    for (int o = 1; o < 32; o <<= 1) {
        int y = __shfl_up_sync(0xFFFFFFFFu, x, o);
        if (lane >= o) x += y;
    }
    if (lane == 31) warp_pref[wid] = x;   // inclusive warp totals
    __syncthreads();
    if (wid == 0) {
        int w = warp_pref[lane];
        #pragma unroll
        for (int o = 1; o < 32; o <<= 1) {
            int y = __shfl_up_sync(0xFFFFFFFFu, w, o);
            if (lane >= o) w += y;
        }
        warp_pref[lane] = w;
    }
    __syncthreads();
    const int thread_excl = (x - local) + (wid > 0 ? warp_pref[wid - 1] : 0);

    // Overwrite hist with exclusive offsets (each thread touches only its bins).
    #pragma unroll
    for (int i = 0; i < 10; i++) {
        int idx = base + i;
        if (idx < FUNC_VOCAB) hist[idx] = thread_excl + cnt[i];
    }
    __syncthreads();

    // Scatter: perm grouped by functor. Order within a bin is nondeterministic
    // but the main kernel writes out[original_b], so the result is invariant.
    for (int b = t; b < BATCH; b += 1024) {
        int f = Xf[b];
        int pos = atomicAdd(&hist[f], 1);
        g_perm[pos] = b;
    }
}

// ---------------------------------------------------------------------------
// out[b] = ctx[b]^T * M[f[b]] * arg[b]
// ---------------------------------------------------------------------------
__global__ __launch_bounds__(NTHREADS)
void matrix_skipgram_kernel(const int* __restrict__ X_argument,
                            const int* __restrict__ X_functor,
                            const int* __restrict__ X_context,
                            const float* __restrict__ noun_matrix,
                            const float* __restrict__ functor_table,
                            const float* __restrict__ context_table,
                            float* __restrict__ out)
{
    const int b = g_perm[blockIdx.x];
    const int t = threadIdx.x;

    __shared__ float s_arg[EMBED];
    __shared__ float s_ctx[EMBED];
    __shared__ float s_red[NTHREADS / 32];

    {
        const float* av = noun_matrix   + (size_t)X_argument[b] * EMBED;
        const float* cv = context_table + (size_t)X_context[b]  * EMBED;
        if (t < EMBED) {
            s_arg[t] = av[t];
            s_ctx[t] = cv[t];
        }
    }
    __syncthreads();

    const float4* __restrict__ M =
        reinterpret_cast<const float4*>(functor_table + (size_t)X_functor[b] * (EMBED * EMBED));

    // Fully unrolled stream: up to 10 independent LDG.128 in flight per thread.
    float acc = 0.0f;
    #pragma unroll
    for (int it = 0; it < ITERS; ++it) {
        const int k = t + it * NTHREADS;
        if (k < VEC4_PER_MAT) {
            const int i  = k / F4_PER_ROW;
            const int j4 = (k - i * F4_PER_ROW) * 4;
            const float4 m = M[k];
            const float c = s_ctx[i];
            float dot = m.x * s_arg[j4]
                      + m.y * s_arg[j4 + 1]
                      + m.z * s_arg[j4 + 2]
                      + m.w * s_arg[j4 + 3];
            acc = fmaf(c, dot, acc);
        }
    }

    #pragma unroll
    for (int o = 16; o > 0; o >>= 1)
        acc += __shfl_xor_sync(0xFFFFFFFFu, acc, o);

    if ((t & 31) == 0)
        s_red[t >> 5] = acc;
    __syncthreads();

    if (t < (NTHREADS / 32)) {
        acc = s_red[t];
        #pragma unroll
        for (int o = (NTHREADS / 64); o > 0; o >>= 1)
            acc += __shfl_xor_sync(0xFFu, acc, o);
        if (t == 0)
            out[b] = acc;
    }
}

extern "C" void kernel_launch(void* const* d_in, const int* in_sizes, int n_in,
                              void* d_out, int out_size)
{
    const int*   X_argument    = (const int*)  d_in[0];
    const int*   X_functor     = (const int*)  d_in[1];
    const int*   X_context     = (const int*)  d_in[2];
    const float* noun_matrix   = (const float*)d_in[3];
    const float* functor_table = (const float*)d_in[4];
    const float* context_table = (const float*)d_in[5];
    float* out = (float*)d_out;

    sort_by_functor_kernel<<<1, 1024>>>(X_functor);
    matrix_skipgram_kernel<<<BATCH, NTHREADS>>>(
        X_argument, X_functor, X_context,
        noun_matrix, functor_table, context_table, out);
}